// round 7
// baseline (speedup 1.0000x reference)
#include <cuda_runtime.h>
#include <cuda_fp16.h>
#include <cstdint>
#include <cstddef>

// ---------------------------------------------------------------------------
// RGCN 2-layer, mean agg, ReLU, L2 norm. N=100000, E=1600000, R=2, 128->128->64.
// Round 7: L1 = CSR gather(128w) + fp16 2-term mma GEMM;
//          L2 = transform-first (T = h@[Wroot|Wrel0|Wrel1]) + fused
//               64-wide gather + mean + root + L2norm finalize.
// ---------------------------------------------------------------------------

#define NN   100000
#define NE   1600000
#define NREL 2
#define CIN  128
#define CHID 128
#define COUT 64

#define SCAN_N (NREL * NN)                  // 200000 buckets
#define SBS    512
#define SNB    ((SCAN_N + SBS - 1) / SBS)   // 391

// Scratch (static device globals; no allocation allowed).
// g_agg doubles as: layer-1 per-(rel,dst) mean features [2][NN][128], then
// layer-2 transformed T [NN][192] (76.8MB <= 102.4MB).
__device__ __align__(128) float g_agg[(size_t)NREL * NN * CIN];   // 102.4 MB
__device__ __align__(128) float g_h[(size_t)NN * CHID];           // 51.2 MB
__device__ int g_icnt[SCAN_N];
__device__ int g_off[SCAN_N];
__device__ int g_cur[SCAN_N];
__device__ int g_bsum[SNB];
__device__ int g_srcs[NE];
__device__ int g_is64;

// ---------------------------------------------------------------------------
// Edge dtype detection (jax x64-disabled silently downcasts int64 -> int32).
// ---------------------------------------------------------------------------
__global__ void detect_kernel(const void* et) {
    const long long* p = (const long long*)et;
    int ok = 1;
    for (int i = 0; i < 512; i++) {
        long long v = p[i];
        if (v < 0 || v >= NREL) { ok = 0; break; }
    }
    g_is64 = ok;
}

__device__ __forceinline__ long long ld_idx(const void* p, long long i, int is64) {
    if (is64) return ((const long long*)p)[i];
    return (long long)((const int*)p)[i];
}

// ---------------------------------------------------------------------------
// CSR build: count -> 2-level scan -> place.
// ---------------------------------------------------------------------------
__global__ void zero_icnt_kernel() {
    int i = blockIdx.x * blockDim.x + threadIdx.x;
    if (i < SCAN_N) g_icnt[i] = 0;
}

__global__ void count_kernel(const void* ei, const void* et) {
    int e = blockIdx.x * blockDim.x + threadIdx.x;
    if (e >= NE) return;
    int is64 = g_is64;
    int dst = (int)ld_idx(ei, (long long)NE + e, is64);
    int r   = (int)ld_idx(et, e, is64);
    atomicAdd(&g_icnt[r * NN + dst], 1);
}

__global__ void scan1_kernel() {
    __shared__ int s[SBS];
    int tid = threadIdx.x;
    int i = blockIdx.x * SBS + tid;
    int v = (i < SCAN_N) ? g_icnt[i] : 0;
    s[tid] = v;
    __syncthreads();
#pragma unroll
    for (int o = 1; o < SBS; o <<= 1) {
        int t = 0;
        if (tid >= o) t = s[tid - o];
        __syncthreads();
        if (tid >= o) s[tid] += t;
        __syncthreads();
    }
    if (i < SCAN_N) g_off[i] = s[tid] - v;
    if (tid == SBS - 1) g_bsum[blockIdx.x] = s[SBS - 1];
}

__global__ void scan2_kernel() {
    __shared__ int s[SBS];
    int tid = threadIdx.x;
    int v = (tid < SNB) ? g_bsum[tid] : 0;
    s[tid] = v;
    __syncthreads();
#pragma unroll
    for (int o = 1; o < SBS; o <<= 1) {
        int t = 0;
        if (tid >= o) t = s[tid - o];
        __syncthreads();
        if (tid >= o) s[tid] += t;
        __syncthreads();
    }
    if (tid < SNB) g_bsum[tid] = s[tid] - v;
}

__global__ void scan3_kernel() {
    int i = blockIdx.x * blockDim.x + threadIdx.x;
    if (i >= SCAN_N) return;
    int o = g_off[i] + g_bsum[i / SBS];
    g_off[i] = o;
    g_cur[i] = o;
}

__global__ void place_kernel(const void* ei, const void* et) {
    int e = blockIdx.x * blockDim.x + threadIdx.x;
    if (e >= NE) return;
    int is64 = g_is64;
    int src = (int)ld_idx(ei, e, is64);
    int dst = (int)ld_idx(ei, (long long)NE + e, is64);
    int r   = (int)ld_idx(et, e, is64);
    int p = atomicAdd(&g_cur[r * NN + dst], 1);
    g_srcs[p] = src;
}

// ---------------------------------------------------------------------------
// Layer-1 gather: one warp per (rel,node) bucket, 128-wide. Mean folded in.
// ---------------------------------------------------------------------------
__global__ void gather_kernel(const float* __restrict__ x) {
    int gt = blockIdx.x * blockDim.x + threadIdx.x;
    int w = gt >> 5;
    int lane = gt & 31;
    if (w >= SCAN_N) return;
    int off = g_off[w];
    int cnt = g_icnt[w];
    float4 acc = make_float4(0.f, 0.f, 0.f, 0.f);
    int e = 0;
    for (; e + 4 <= cnt; e += 4) {
        int s0 = g_srcs[off + e];
        int s1 = g_srcs[off + e + 1];
        int s2 = g_srcs[off + e + 2];
        int s3 = g_srcs[off + e + 3];
        float4 v0 = ((const float4*)(x + (size_t)s0 * CIN))[lane];
        float4 v1 = ((const float4*)(x + (size_t)s1 * CIN))[lane];
        float4 v2 = ((const float4*)(x + (size_t)s2 * CIN))[lane];
        float4 v3 = ((const float4*)(x + (size_t)s3 * CIN))[lane];
        acc.x += (v0.x + v1.x) + (v2.x + v3.x);
        acc.y += (v0.y + v1.y) + (v2.y + v3.y);
        acc.z += (v0.z + v1.z) + (v2.z + v3.z);
        acc.w += (v0.w + v1.w) + (v2.w + v3.w);
    }
    for (; e < cnt; e++) {
        int s0 = g_srcs[off + e];
        float4 v0 = ((const float4*)(x + (size_t)s0 * CIN))[lane];
        acc.x += v0.x; acc.y += v0.y; acc.z += v0.z; acc.w += v0.w;
    }
    float s = 1.0f / (float)(cnt > 0 ? cnt : 1);
    acc.x *= s; acc.y *= s; acc.z *= s; acc.w *= s;
    ((float4*)(g_agg + (size_t)w * CIN))[lane] = acc;
}

// ---------------------------------------------------------------------------
// fp16 2-term split helpers: A = Ah + Al (each fp16), B = fp16(B).
// ---------------------------------------------------------------------------
__device__ __forceinline__ uint32_t packh2(float a, float b) {
    __half2 h = __floats2half2_rn(a, b);
    return *(uint32_t*)&h;
}
__device__ __forceinline__ void split2h(float a, float b, uint32_t& h, uint32_t& l) {
    __half2 hh = __floats2half2_rn(a, b);
    h = *(uint32_t*)&hh;
    l = packh2(a - __half2float(__low2half(hh)),
               b - __half2float(__high2half(hh)));
}

__device__ __forceinline__ void mma_f16(float* c, uint32_t a0, uint32_t a1,
                                        uint32_t a2, uint32_t a3,
                                        uint32_t b0, uint32_t b1) {
    asm volatile(
        "mma.sync.aligned.m16n8k16.row.col.f32.f16.f16.f32 "
        "{%0,%1,%2,%3}, {%4,%5,%6,%7}, {%8,%9}, {%0,%1,%2,%3};"
        : "+f"(c[0]), "+f"(c[1]), "+f"(c[2]), "+f"(c[3])
        : "r"(a0), "r"(a1), "r"(a2), "r"(a3), "r"(b0), "r"(b1));
}

// ---------------------------------------------------------------------------
// Layer-1 combine GEMM (fp16 2-term split):
//   h = relu( [x | agg0 | agg1] @ [W1root;W1rel0;W1rel1] + b1 )
// 256 threads = 8 warps; warp w owns rows [16w,16w+16) x 128 cols.
// K=384 in 12 chunks of 32.
// ---------------------------------------------------------------------------
__global__ void __launch_bounds__(256)
combine1_kernel(const float* __restrict__ Ax,
                const float* __restrict__ Wroot,
                const float* __restrict__ Wrel,
                const float* __restrict__ bias) {
    constexpr int OUTC = CHID;
    constexpr int NT = OUTC / 8;          // 16
    __shared__ uint32_t As_hi[128][20];   // [row][k-word], 2 f16/word, pad 4
    __shared__ uint32_t As_lo[128][20];
    __shared__ uint32_t Bs[OUTC][20];     // [n][k-word], fp16 only

    int tid  = threadIdx.x;
    int wid  = tid >> 5;
    int lane = tid & 31;
    int m0   = blockIdx.x * 128;
    int mrow = wid * 16;

    float acc[NT][4];
#pragma unroll
    for (int i = 0; i < NT; i++)
#pragma unroll
        for (int j = 0; j < 4; j++) acc[i][j] = 0.f;

    for (int c = 0; c < 12; c++) {
        int seg  = c >> 2;            // 0: x, 1/2: relation means
        int krel = (c & 3) * 32;

        if (tid < 128) {
            const float* Asrc = (seg == 0) ? Ax : (g_agg + (size_t)(seg - 1) * NN * 128);
            int node = m0 + tid;
            bool valid = (node < NN);
            const float4* src = (const float4*)(Asrc + (size_t)node * 128 + krel);
#pragma unroll
            for (int i = 0; i < 8; i++) {
                float4 v = valid ? src[i] : make_float4(0.f, 0.f, 0.f, 0.f);
                uint32_t h0, l0, h1, l1;
                split2h(v.x, v.y, h0, l0);
                split2h(v.z, v.w, h1, l1);
                As_hi[tid][2 * i + 0] = h0;
                As_hi[tid][2 * i + 1] = h1;
                As_lo[tid][2 * i + 0] = l0;
                As_lo[tid][2 * i + 1] = l1;
            }
        } else {
            const float* Bsrc = (seg == 0) ? Wroot : (Wrel + (size_t)(seg - 1) * 128 * OUTC);
            int n = tid - 128;
#pragma unroll
            for (int g = 0; g < 16; g++) {
                float v0 = Bsrc[(size_t)(krel + 2 * g + 0) * OUTC + n];
                float v1 = Bsrc[(size_t)(krel + 2 * g + 1) * OUTC + n];
                Bs[n][g] = packh2(v0, v1);
            }
        }
        __syncthreads();

#pragma unroll
        for (int k16 = 0; k16 < 2; k16++) {
            int wk = k16 * 8 + (lane & 3);
            int r0 = mrow + (lane >> 2);
            uint32_t ah0 = As_hi[r0][wk],     ah1 = As_hi[r0 + 8][wk];
            uint32_t ah2 = As_hi[r0][wk + 4], ah3 = As_hi[r0 + 8][wk + 4];
            uint32_t al0 = As_lo[r0][wk],     al1 = As_lo[r0 + 8][wk];
            uint32_t al2 = As_lo[r0][wk + 4], al3 = As_lo[r0 + 8][wk + 4];
#pragma unroll
            for (int n8 = 0; n8 < NT; n8++) {
                int nr = n8 * 8 + (lane >> 2);
                uint32_t b0 = Bs[nr][wk], b1 = Bs[nr][wk + 4];
                mma_f16(acc[n8], ah0, ah1, ah2, ah3, b0, b1);
                mma_f16(acc[n8], al0, al1, al2, al3, b0, b1);
            }
        }
        __syncthreads();
    }

    int r0 = m0 + mrow + (lane >> 2);
#pragma unroll
    for (int n8 = 0; n8 < NT; n8++) {
        int col = n8 * 8 + 2 * (lane & 3);
        float b0 = bias[col], b1 = bias[col + 1];
        float2 o0, o1;
        o0.x = fmaxf(acc[n8][0] + b0, 0.f); o0.y = fmaxf(acc[n8][1] + b1, 0.f);
        o1.x = fmaxf(acc[n8][2] + b0, 0.f); o1.y = fmaxf(acc[n8][3] + b1, 0.f);
        if (r0 < NN)     *(float2*)(g_h + (size_t)r0 * OUTC + col) = o0;
        if (r0 + 8 < NN) *(float2*)(g_h + (size_t)(r0 + 8) * OUTC + col) = o1;
    }
}

// ---------------------------------------------------------------------------
// Layer-2 transform GEMM (fp16 2-term split):
//   T = h @ [W2root | W2rel0 | W2rel1]  (+ b2 on cols [0,64))
// T is [NN][192] fp32, stored in g_agg scratch. Grid (MT, 2): 96 cols/CTA.
// ---------------------------------------------------------------------------
__global__ void __launch_bounds__(256)
transform2_kernel(const float* __restrict__ Wroot,
                  const float* __restrict__ Wrel,
                  const float* __restrict__ bias) {
    constexpr int BN = 96;
    constexpr int NT = BN / 8;            // 12
    __shared__ uint32_t As_hi[128][20];
    __shared__ uint32_t As_lo[128][20];
    __shared__ uint32_t Bs[BN][20];

    float* T = g_agg;                     // [NN][192]

    int tid  = threadIdx.x;
    int wid  = tid >> 5;
    int lane = tid & 31;
    int m0   = blockIdx.x * 128;
    int n0   = blockIdx.y * BN;
    int mrow = wid * 16;

    float acc[NT][4];
#pragma unroll
    for (int i = 0; i < NT; i++)
#pragma unroll
        for (int j = 0; j < 4; j++) acc[i][j] = 0.f;

    // Resolve this thread's B column source (only threads 128..224 load B).
    const float* Bp = nullptr;
    int bc = 0;
    if (tid >= 128 && tid < 128 + BN) {
        int ncol = n0 + (tid - 128);
        if (ncol < 64)       { Bp = Wroot;           bc = ncol; }
        else if (ncol < 128) { Bp = Wrel;            bc = ncol - 64; }
        else                 { Bp = Wrel + 128 * 64; bc = ncol - 128; }
    }

    for (int c = 0; c < 4; c++) {
        int krel = c * 32;

        if (tid < 128) {
            int node = m0 + tid;
            bool valid = (node < NN);
            const float4* src = (const float4*)(g_h + (size_t)node * 128 + krel);
#pragma unroll
            for (int i = 0; i < 8; i++) {
                float4 v = valid ? src[i] : make_float4(0.f, 0.f, 0.f, 0.f);
                uint32_t h0, l0, h1, l1;
                split2h(v.x, v.y, h0, l0);
                split2h(v.z, v.w, h1, l1);
                As_hi[tid][2 * i + 0] = h0;
                As_hi[tid][2 * i + 1] = h1;
                As_lo[tid][2 * i + 0] = l0;
                As_lo[tid][2 * i + 1] = l1;
            }
        } else if (Bp) {
            int n = tid - 128;
#pragma unroll
            for (int g = 0; g < 16; g++) {
                float v0 = Bp[(size_t)(krel + 2 * g + 0) * 64 + bc];
                float v1 = Bp[(size_t)(krel + 2 * g + 1) * 64 + bc];
                Bs[n][g] = packh2(v0, v1);
            }
        }
        __syncthreads();

#pragma unroll
        for (int k16 = 0; k16 < 2; k16++) {
            int wk = k16 * 8 + (lane & 3);
            int r0 = mrow + (lane >> 2);
            uint32_t ah0 = As_hi[r0][wk],     ah1 = As_hi[r0 + 8][wk];
            uint32_t ah2 = As_hi[r0][wk + 4], ah3 = As_hi[r0 + 8][wk + 4];
            uint32_t al0 = As_lo[r0][wk],     al1 = As_lo[r0 + 8][wk];
            uint32_t al2 = As_lo[r0][wk + 4], al3 = As_lo[r0 + 8][wk + 4];
#pragma unroll
            for (int n8 = 0; n8 < NT; n8++) {
                int nr = n8 * 8 + (lane >> 2);
                uint32_t b0 = Bs[nr][wk], b1 = Bs[nr][wk + 4];
                mma_f16(acc[n8], ah0, ah1, ah2, ah3, b0, b1);
                mma_f16(acc[n8], al0, al1, al2, al3, b0, b1);
            }
        }
        __syncthreads();
    }

    int r0 = m0 + mrow + (lane >> 2);
#pragma unroll
    for (int n8 = 0; n8 < NT; n8++) {
        int col = n0 + n8 * 8 + 2 * (lane & 3);
        float b0 = (col < 64) ? bias[col] : 0.f;
        float b1 = (col + 1 < 64) ? bias[col + 1] : 0.f;
        float2 o0, o1;
        o0.x = acc[n8][0] + b0; o0.y = acc[n8][1] + b1;
        o1.x = acc[n8][2] + b0; o1.y = acc[n8][3] + b1;
        if (r0 < NN)     *(float2*)(T + (size_t)r0 * 192 + col) = o0;
        if (r0 + 8 < NN) *(float2*)(T + (size_t)(r0 + 8) * 192 + col) = o1;
    }
}

// ---------------------------------------------------------------------------
// Finalize: one warp per node. out = l2norm( T[node][0:64]
//            + sum_r mean_{e in bucket(r,node)} T[src_e][64+64r : 128+64r] ).
// Per-edge read = 256B (one 64-wide slice). Gather + mean + norm fused.
// ---------------------------------------------------------------------------
__global__ void finalize_kernel(float* __restrict__ out) {
    const float* __restrict__ T = g_agg;   // [NN][192]
    long long gtid = (long long)blockIdx.x * blockDim.x + threadIdx.x;
    int node = (int)(gtid >> 5);
    int lane = (int)(gtid & 31);
    if (node >= NN) return;

    float2 acc = *(const float2*)(T + (size_t)node * 192 + 2 * lane);

#pragma unroll
    for (int r = 0; r < NREL; r++) {
        int w = r * NN + node;
        int off = g_off[w];
        int cnt = g_icnt[w];
        int coff = 64 + r * 64 + 2 * lane;
        float2 s = make_float2(0.f, 0.f);
        int e = 0;
        for (; e + 2 <= cnt; e += 2) {
            int s0 = g_srcs[off + e];
            int s1 = g_srcs[off + e + 1];
            float2 v0 = *(const float2*)(T + (size_t)s0 * 192 + coff);
            float2 v1 = *(const float2*)(T + (size_t)s1 * 192 + coff);
            s.x += v0.x + v1.x;
            s.y += v0.y + v1.y;
        }
        if (e < cnt) {
            int s0 = g_srcs[off + e];
            float2 v0 = *(const float2*)(T + (size_t)s0 * 192 + coff);
            s.x += v0.x; s.y += v0.y;
        }
        float inv = 1.0f / (float)(cnt > 0 ? cnt : 1);
        acc.x += s.x * inv;
        acc.y += s.y * inv;
    }

    float ss = acc.x * acc.x + acc.y * acc.y;
#pragma unroll
    for (int o = 16; o; o >>= 1) ss += __shfl_xor_sync(0xFFFFFFFFu, ss, o);
    float sc = 1.0f / fmaxf(sqrtf(ss), 1e-12f);
    float2 o2 = make_float2(acc.x * sc, acc.y * sc);
    *(float2*)(out + (size_t)node * COUT + 2 * lane) = o2;
}

// ---------------------------------------------------------------------------
extern "C" void kernel_launch(void* const* d_in, const int* in_sizes, int n_in,
                              void* d_out, int out_size) {
    const float* x       = (const float*)d_in[0];
    const void*  ei      = d_in[1];
    const void*  et      = d_in[2];
    const float* W1_rel  = (const float*)d_in[3];
    const float* W1_root = (const float*)d_in[4];
    const float* b1      = (const float*)d_in[5];
    const float* W2_rel  = (const float*)d_in[6];
    const float* W2_root = (const float*)d_in[7];
    const float* b2      = (const float*)d_in[8];
    float* out = (float*)d_out;

    const int MT = (NN + 127) / 128;   // 782

    detect_kernel<<<1, 1>>>(et);

    // CSR build (once; reused by layer-1 gather and finalize)
    zero_icnt_kernel<<<(SCAN_N + 255) / 256, 256>>>();
    count_kernel<<<(NE + 255) / 256, 256>>>(ei, et);
    scan1_kernel<<<SNB, SBS>>>();
    scan2_kernel<<<1, SBS>>>();
    scan3_kernel<<<(SCAN_N + 255) / 256, 256>>>();
    place_kernel<<<(NE + 255) / 256, 256>>>(ei, et);

    // Layer 1: gather(x, 128-wide) -> combine GEMM -> g_h
    gather_kernel<<<SCAN_N * 32 / 256, 256>>>(x);
    combine1_kernel<<<MT, 256>>>(x, W1_root, W1_rel, b1);

    // Layer 2: transform-first (T = h@W, into g_agg scratch), then fused
    // 64-wide gather + mean + root + L2 normalize.
    transform2_kernel<<<dim3(MT, 2), 256>>>(W2_root, W2_rel, b2);
    finalize_kernel<<<(NN * 32 + 255) / 256, 256>>>(out);
}

// round 8
// speedup vs baseline: 1.2685x; 1.2685x over previous
#include <cuda_runtime.h>
#include <cuda_fp16.h>
#include <cstdint>
#include <cstddef>

// ---------------------------------------------------------------------------
// RGCN 2-layer, mean agg, ReLU, L2 norm. N=100000, E=1600000, R=2, 128->128->64.
// Round 8: exact R6 structure (best known), single change: fp16 2-term split
// GEMM (D = Ah*B + Al*B) replacing bf16 3-term.
// ---------------------------------------------------------------------------

#define NN   100000
#define NE   1600000
#define NREL 2
#define CIN  128
#define CHID 128
#define COUT 64

#define SCAN_N (NREL * NN)                  // 200000 buckets
#define SBS    512
#define SNB    ((SCAN_N + SBS - 1) / SBS)   // 391

// Scratch (static device globals; no allocation allowed).
__device__ __align__(128) float g_agg[(size_t)NREL * NN * CIN];   // 102.4 MB
__device__ __align__(128) float g_h[(size_t)NN * CHID];           // 51.2 MB
__device__ int g_icnt[SCAN_N];
__device__ int g_off[SCAN_N];
__device__ int g_cur[SCAN_N];
__device__ int g_bsum[SNB];
__device__ int g_srcs[NE];
__device__ int g_is64;

// ---------------------------------------------------------------------------
// Edge dtype detection (jax x64-disabled silently downcasts int64 -> int32).
// ---------------------------------------------------------------------------
__global__ void detect_kernel(const void* et) {
    const long long* p = (const long long*)et;
    int ok = 1;
    for (int i = 0; i < 512; i++) {
        long long v = p[i];
        if (v < 0 || v >= NREL) { ok = 0; break; }
    }
    g_is64 = ok;
}

__device__ __forceinline__ long long ld_idx(const void* p, long long i, int is64) {
    if (is64) return ((const long long*)p)[i];
    return (long long)((const int*)p)[i];
}

// ---------------------------------------------------------------------------
// CSR build: count -> 2-level scan -> place.
// ---------------------------------------------------------------------------
__global__ void zero_icnt_kernel() {
    int i = blockIdx.x * blockDim.x + threadIdx.x;
    if (i < SCAN_N) g_icnt[i] = 0;
}

__global__ void count_kernel(const void* ei, const void* et) {
    int e = blockIdx.x * blockDim.x + threadIdx.x;
    if (e >= NE) return;
    int is64 = g_is64;
    int dst = (int)ld_idx(ei, (long long)NE + e, is64);
    int r   = (int)ld_idx(et, e, is64);
    atomicAdd(&g_icnt[r * NN + dst], 1);
}

__global__ void scan1_kernel() {
    __shared__ int s[SBS];
    int tid = threadIdx.x;
    int i = blockIdx.x * SBS + tid;
    int v = (i < SCAN_N) ? g_icnt[i] : 0;
    s[tid] = v;
    __syncthreads();
#pragma unroll
    for (int o = 1; o < SBS; o <<= 1) {
        int t = 0;
        if (tid >= o) t = s[tid - o];
        __syncthreads();
        if (tid >= o) s[tid] += t;
        __syncthreads();
    }
    if (i < SCAN_N) g_off[i] = s[tid] - v;
    if (tid == SBS - 1) g_bsum[blockIdx.x] = s[SBS - 1];
}

__global__ void scan2_kernel() {
    __shared__ int s[SBS];
    int tid = threadIdx.x;
    int v = (tid < SNB) ? g_bsum[tid] : 0;
    s[tid] = v;
    __syncthreads();
#pragma unroll
    for (int o = 1; o < SBS; o <<= 1) {
        int t = 0;
        if (tid >= o) t = s[tid - o];
        __syncthreads();
        if (tid >= o) s[tid] += t;
        __syncthreads();
    }
    if (tid < SNB) g_bsum[tid] = s[tid] - v;
}

__global__ void scan3_kernel() {
    int i = blockIdx.x * blockDim.x + threadIdx.x;
    if (i >= SCAN_N) return;
    int o = g_off[i] + g_bsum[i / SBS];
    g_off[i] = o;
    g_cur[i] = o;
}

__global__ void place_kernel(const void* ei, const void* et) {
    int e = blockIdx.x * blockDim.x + threadIdx.x;
    if (e >= NE) return;
    int is64 = g_is64;
    int src = (int)ld_idx(ei, e, is64);
    int dst = (int)ld_idx(ei, (long long)NE + e, is64);
    int r   = (int)ld_idx(et, e, is64);
    int p = atomicAdd(&g_cur[r * NN + dst], 1);
    g_srcs[p] = src;
}

// ---------------------------------------------------------------------------
// Gather-aggregate: one warp per (rel,node) bucket. Mean folded in.
// ---------------------------------------------------------------------------
__global__ void gather_kernel(const float* __restrict__ x, int use_h) {
    int gt = blockIdx.x * blockDim.x + threadIdx.x;
    int w = gt >> 5;
    int lane = gt & 31;
    if (w >= SCAN_N) return;
    const float* __restrict__ base = use_h ? g_h : x;
    int off = g_off[w];
    int cnt = g_icnt[w];
    float4 acc = make_float4(0.f, 0.f, 0.f, 0.f);
    int e = 0;
    for (; e + 4 <= cnt; e += 4) {
        int s0 = g_srcs[off + e];
        int s1 = g_srcs[off + e + 1];
        int s2 = g_srcs[off + e + 2];
        int s3 = g_srcs[off + e + 3];
        float4 v0 = ((const float4*)(base + (size_t)s0 * CIN))[lane];
        float4 v1 = ((const float4*)(base + (size_t)s1 * CIN))[lane];
        float4 v2 = ((const float4*)(base + (size_t)s2 * CIN))[lane];
        float4 v3 = ((const float4*)(base + (size_t)s3 * CIN))[lane];
        acc.x += (v0.x + v1.x) + (v2.x + v3.x);
        acc.y += (v0.y + v1.y) + (v2.y + v3.y);
        acc.z += (v0.z + v1.z) + (v2.z + v3.z);
        acc.w += (v0.w + v1.w) + (v2.w + v3.w);
    }
    for (; e < cnt; e++) {
        int s0 = g_srcs[off + e];
        float4 v0 = ((const float4*)(base + (size_t)s0 * CIN))[lane];
        acc.x += v0.x; acc.y += v0.y; acc.z += v0.z; acc.w += v0.w;
    }
    float s = 1.0f / (float)(cnt > 0 ? cnt : 1);
    acc.x *= s; acc.y *= s; acc.z *= s; acc.w *= s;
    ((float4*)(g_agg + (size_t)w * CIN))[lane] = acc;
}

// ---------------------------------------------------------------------------
// fp16 2-term split helpers: A = Ah + Al (each fp16), B = fp16(B).
// ---------------------------------------------------------------------------
__device__ __forceinline__ uint32_t packh2(float a, float b) {
    __half2 h = __floats2half2_rn(a, b);
    return *(uint32_t*)&h;
}
__device__ __forceinline__ void split2h(float a, float b, uint32_t& h, uint32_t& l) {
    __half2 hh = __floats2half2_rn(a, b);
    h = *(uint32_t*)&hh;
    l = packh2(a - __half2float(__low2half(hh)),
               b - __half2float(__high2half(hh)));
}

__device__ __forceinline__ void mma_f16(float* c, uint32_t a0, uint32_t a1,
                                        uint32_t a2, uint32_t a3,
                                        uint32_t b0, uint32_t b1) {
    asm volatile(
        "mma.sync.aligned.m16n8k16.row.col.f32.f16.f16.f32 "
        "{%0,%1,%2,%3}, {%4,%5,%6,%7}, {%8,%9}, {%0,%1,%2,%3};"
        : "+f"(c[0]), "+f"(c[1]), "+f"(c[2]), "+f"(c[3])
        : "r"(a0), "r"(a1), "r"(a2), "r"(a3), "r"(b0), "r"(b1));
}

// ---------------------------------------------------------------------------
// Fused combine GEMM, fp16 2-term split on tensor cores:
//   out = act( [x | agg0 | agg1] @ [Wroot;Wrel0;Wrel1] + b )
//   D = Ah*B + Al*B  (fp32 accumulate; A err ~2^-22, B err ~2^-11)
// 256 threads = 8 warps; warp w owns rows [16w,16w+16) x all OUTC cols.
// K=384 in 12 chunks of 32. Smem rows padded to 20 words (80B).
// ---------------------------------------------------------------------------
template <int OUTC, bool LAYER1>
__global__ void __launch_bounds__(256)
combine_mma_kernel(const float* __restrict__ Ax,
                   const float* __restrict__ Wroot,
                   const float* __restrict__ Wrel,
                   const float* __restrict__ bias,
                   float* __restrict__ out_param) {
    constexpr int NT = OUTC / 8;          // n8 tiles per warp
    __shared__ uint32_t As_hi[128][20];   // [row][k-word], 2 f16/word, pad 4
    __shared__ uint32_t As_lo[128][20];
    __shared__ uint32_t Bs[OUTC][20];     // [n][k-word], single fp16

    const float* A0  = LAYER1 ? Ax : g_h;
    float*       out = LAYER1 ? g_h : out_param;

    int tid  = threadIdx.x;
    int wid  = tid >> 5;
    int lane = tid & 31;
    int m0   = blockIdx.x * 128;
    int mrow = wid * 16;

    float acc[NT][4];
#pragma unroll
    for (int i = 0; i < NT; i++)
#pragma unroll
        for (int j = 0; j < 4; j++) acc[i][j] = 0.f;

    for (int c = 0; c < 12; c++) {
        int seg  = c >> 2;            // 0: root input, 1/2: relation means
        int krel = (c & 3) * 32;      // k offset within the 128-wide segment

        if (tid < 128) {
            // A loader: thread t = row t; 32 floats -> 16 hi + 16 lo words.
            const float* Asrc = (seg == 0) ? A0 : (g_agg + (size_t)(seg - 1) * NN * 128);
            int node = m0 + tid;
            bool valid = (node < NN);
            const float4* src = (const float4*)(Asrc + (size_t)node * 128 + krel);
#pragma unroll
            for (int i = 0; i < 8; i++) {
                float4 v = valid ? src[i] : make_float4(0.f, 0.f, 0.f, 0.f);
                uint32_t h0, l0, h1, l1;
                split2h(v.x, v.y, h0, l0);
                split2h(v.z, v.w, h1, l1);
                As_hi[tid][2 * i + 0] = h0;
                As_hi[tid][2 * i + 1] = h1;
                As_lo[tid][2 * i + 0] = l0;
                As_lo[tid][2 * i + 1] = l1;
            }
        } else if (tid - 128 < OUTC) {
            // B loader: thread owns output col n; reads W[k][n] (coalesced
            // across threads per k), transposes into [n][k] fp16 tile.
            const float* Bsrc = (seg == 0) ? Wroot : (Wrel + (size_t)(seg - 1) * 128 * OUTC);
            int n = tid - 128;
#pragma unroll
            for (int g = 0; g < 16; g++) {
                float v0 = Bsrc[(size_t)(krel + 2 * g + 0) * OUTC + n];
                float v1 = Bsrc[(size_t)(krel + 2 * g + 1) * OUTC + n];
                Bs[n][g] = packh2(v0, v1);
            }
        }
        __syncthreads();

#pragma unroll
        for (int k16 = 0; k16 < 2; k16++) {
            int wk = k16 * 8 + (lane & 3);
            int r0 = mrow + (lane >> 2);
            uint32_t ah0 = As_hi[r0][wk],     ah1 = As_hi[r0 + 8][wk];
            uint32_t ah2 = As_hi[r0][wk + 4], ah3 = As_hi[r0 + 8][wk + 4];
            uint32_t al0 = As_lo[r0][wk],     al1 = As_lo[r0 + 8][wk];
            uint32_t al2 = As_lo[r0][wk + 4], al3 = As_lo[r0 + 8][wk + 4];
#pragma unroll
            for (int n8 = 0; n8 < NT; n8++) {
                int nr = n8 * 8 + (lane >> 2);
                uint32_t b0 = Bs[nr][wk], b1 = Bs[nr][wk + 4];
                mma_f16(acc[n8], ah0, ah1, ah2, ah3, b0, b1);
                mma_f16(acc[n8], al0, al1, al2, al3, b0, b1);
            }
        }
        __syncthreads();
    }

    // Epilogue: c0={r, 2t}, c1={r, 2t+1}, c2/c3 at row+8.
    int r0 = m0 + mrow + (lane >> 2);
#pragma unroll
    for (int n8 = 0; n8 < NT; n8++) {
        int col = n8 * 8 + 2 * (lane & 3);
        float b0 = bias[col], b1 = bias[col + 1];
        float2 o0, o1;
        o0.x = acc[n8][0] + b0; o0.y = acc[n8][1] + b1;
        o1.x = acc[n8][2] + b0; o1.y = acc[n8][3] + b1;
        if (LAYER1) {
            o0.x = fmaxf(o0.x, 0.f); o0.y = fmaxf(o0.y, 0.f);
            o1.x = fmaxf(o1.x, 0.f); o1.y = fmaxf(o1.y, 0.f);
        }
        if (r0 < NN)     *(float2*)(out + (size_t)r0 * OUTC + col) = o0;
        if (r0 + 8 < NN) *(float2*)(out + (size_t)(r0 + 8) * OUTC + col) = o1;
    }
}

// ---------------------------------------------------------------------------
// Row L2 normalize: one warp per node.
// ---------------------------------------------------------------------------
__global__ void normalize_kernel(float* __restrict__ out) {
    long long gtid = (long long)blockIdx.x * blockDim.x + threadIdx.x;
    int node = (int)(gtid >> 5);
    int lane = (int)(gtid & 31);
    if (node >= NN) return;
    float2* row = (float2*)(out + (size_t)node * COUT);
    float2 v = row[lane];
    float ss = v.x * v.x + v.y * v.y;
#pragma unroll
    for (int o = 16; o; o >>= 1) ss += __shfl_xor_sync(0xFFFFFFFFu, ss, o);
    float s = 1.0f / fmaxf(sqrtf(ss), 1e-12f);
    v.x *= s; v.y *= s;
    row[lane] = v;
}

// ---------------------------------------------------------------------------
extern "C" void kernel_launch(void* const* d_in, const int* in_sizes, int n_in,
                              void* d_out, int out_size) {
    const float* x       = (const float*)d_in[0];
    const void*  ei      = d_in[1];
    const void*  et      = d_in[2];
    const float* W1_rel  = (const float*)d_in[3];
    const float* W1_root = (const float*)d_in[4];
    const float* b1      = (const float*)d_in[5];
    const float* W2_rel  = (const float*)d_in[6];
    const float* W2_root = (const float*)d_in[7];
    const float* b2      = (const float*)d_in[8];
    float* out = (float*)d_out;

    const int MT = (NN + 127) / 128;   // 782

    detect_kernel<<<1, 1>>>(et);

    // CSR build (once; reused by both layers)
    zero_icnt_kernel<<<(SCAN_N + 255) / 256, 256>>>();
    count_kernel<<<(NE + 255) / 256, 256>>>(ei, et);
    scan1_kernel<<<SNB, SBS>>>();
    scan2_kernel<<<1, SBS>>>();
    scan3_kernel<<<(SCAN_N + 255) / 256, 256>>>();
    place_kernel<<<(NE + 255) / 256, 256>>>(ei, et);

    // Layer 1
    gather_kernel<<<SCAN_N * 32 / 256, 256>>>(x, 0);
    combine_mma_kernel<CHID, true><<<MT, 256>>>(x, W1_root, W1_rel, b1, nullptr);

    // Layer 2
    gather_kernel<<<SCAN_N * 32 / 256, 256>>>(x, 1);
    combine_mma_kernel<COUT, false><<<MT, 256>>>(nullptr, W2_root, W2_rel, b2, out);

    normalize_kernel<<<(NN * 32 + 255) / 256, 256>>>(out);
}

// round 9
// speedup vs baseline: 1.4825x; 1.1687x over previous
#include <cuda_runtime.h>
#include <cuda_fp16.h>
#include <cstdint>
#include <cstddef>

// ---------------------------------------------------------------------------
// RGCN 2-layer, mean agg, ReLU, L2 norm. N=100000, E=1600000, R=2, 128->128->64.
// Round 9: fp16 feature rows for the gathers (halve scatter/gather traffic);
// agg stored fp16 -> GEMM agg segments are single-term MMA (no split).
// Root/x path stays fp32 2-term.
// ---------------------------------------------------------------------------

#define NN   100000
#define NE   1600000
#define NREL 2
#define CIN  128
#define CHID 128
#define COUT 64

#define SCAN_N (NREL * NN)                  // 200000 buckets
#define SBS    512
#define SNB    ((SCAN_N + SBS - 1) / SBS)   // 391

// Scratch (static device globals; no allocation allowed).
__device__ __align__(128) __half g_agg16[(size_t)NREL * NN * CIN]; // 51.2 MB
__device__ __align__(128) float  g_h[(size_t)NN * CHID];           // 51.2 MB
__device__ __align__(128) __half g_h16[(size_t)NN * CHID];         // 25.6 MB
__device__ __align__(128) __half g_x16[(size_t)NN * CIN];          // 25.6 MB
__device__ int g_icnt[SCAN_N];
__device__ int g_off[SCAN_N];
__device__ int g_cur[SCAN_N];
__device__ int g_bsum[SNB];
__device__ int g_srcs[NE];
__device__ int g_is64;

// ---------------------------------------------------------------------------
// Edge dtype detection (jax x64-disabled silently downcasts int64 -> int32).
// ---------------------------------------------------------------------------
__global__ void detect_kernel(const void* et) {
    const long long* p = (const long long*)et;
    int ok = 1;
    for (int i = 0; i < 512; i++) {
        long long v = p[i];
        if (v < 0 || v >= NREL) { ok = 0; break; }
    }
    g_is64 = ok;
}

__device__ __forceinline__ long long ld_idx(const void* p, long long i, int is64) {
    if (is64) return ((const long long*)p)[i];
    return (long long)((const int*)p)[i];
}

// ---------------------------------------------------------------------------
// x -> fp16 copy (once).
// ---------------------------------------------------------------------------
__global__ void cvt_x_kernel(const float* __restrict__ x) {
    size_t i = (size_t)blockIdx.x * blockDim.x + threadIdx.x;   // word of 2
    const size_t n2 = (size_t)NN * CIN / 2;
    if (i >= n2) return;
    float2 v = ((const float2*)x)[i];
    __half2 h = __floats2half2_rn(v.x, v.y);
    ((__half2*)g_x16)[i] = h;
}

// ---------------------------------------------------------------------------
// CSR build: count -> 2-level scan -> place.
// ---------------------------------------------------------------------------
__global__ void zero_icnt_kernel() {
    int i = blockIdx.x * blockDim.x + threadIdx.x;
    if (i < SCAN_N) g_icnt[i] = 0;
}

__global__ void count_kernel(const void* ei, const void* et) {
    int e = blockIdx.x * blockDim.x + threadIdx.x;
    if (e >= NE) return;
    int is64 = g_is64;
    int dst = (int)ld_idx(ei, (long long)NE + e, is64);
    int r   = (int)ld_idx(et, e, is64);
    atomicAdd(&g_icnt[r * NN + dst], 1);
}

__global__ void scan1_kernel() {
    __shared__ int s[SBS];
    int tid = threadIdx.x;
    int i = blockIdx.x * SBS + tid;
    int v = (i < SCAN_N) ? g_icnt[i] : 0;
    s[tid] = v;
    __syncthreads();
#pragma unroll
    for (int o = 1; o < SBS; o <<= 1) {
        int t = 0;
        if (tid >= o) t = s[tid - o];
        __syncthreads();
        if (tid >= o) s[tid] += t;
        __syncthreads();
    }
    if (i < SCAN_N) g_off[i] = s[tid] - v;
    if (tid == SBS - 1) g_bsum[blockIdx.x] = s[SBS - 1];
}

__global__ void scan2_kernel() {
    __shared__ int s[SBS];
    int tid = threadIdx.x;
    int v = (tid < SNB) ? g_bsum[tid] : 0;
    s[tid] = v;
    __syncthreads();
#pragma unroll
    for (int o = 1; o < SBS; o <<= 1) {
        int t = 0;
        if (tid >= o) t = s[tid - o];
        __syncthreads();
        if (tid >= o) s[tid] += t;
        __syncthreads();
    }
    if (tid < SNB) g_bsum[tid] = s[tid] - v;
}

__global__ void scan3_kernel() {
    int i = blockIdx.x * blockDim.x + threadIdx.x;
    if (i >= SCAN_N) return;
    int o = g_off[i] + g_bsum[i / SBS];
    g_off[i] = o;
    g_cur[i] = o;
}

__global__ void place_kernel(const void* ei, const void* et) {
    int e = blockIdx.x * blockDim.x + threadIdx.x;
    if (e >= NE) return;
    int is64 = g_is64;
    int src = (int)ld_idx(ei, e, is64);
    int dst = (int)ld_idx(ei, (long long)NE + e, is64);
    int r   = (int)ld_idx(et, e, is64);
    int p = atomicAdd(&g_cur[r * NN + dst], 1);
    g_srcs[p] = src;
}

// ---------------------------------------------------------------------------
// Gather-aggregate over fp16 rows: one warp per (rel,node) bucket.
// Lane l owns halves [4l,4l+4) (uint2 = 8B). fp32 accumulate, fp16 store.
// ---------------------------------------------------------------------------
__global__ void gather_kernel(int use_h) {
    int gt = blockIdx.x * blockDim.x + threadIdx.x;
    int w = gt >> 5;
    int lane = gt & 31;
    if (w >= SCAN_N) return;
    const __half2* __restrict__ base = (const __half2*)(use_h ? g_h16 : g_x16);
    int off = g_off[w];
    int cnt = g_icnt[w];
    float2 a0 = make_float2(0.f, 0.f), a1 = a0;
    int e = 0;
    for (; e + 4 <= cnt; e += 4) {
#pragma unroll
        for (int u = 0; u < 4; u++) {
            int sN = g_srcs[off + e + u];
            __half2 h0 = base[(size_t)sN * 64 + 2 * lane];
            __half2 h1 = base[(size_t)sN * 64 + 2 * lane + 1];
            float2 f0 = __half22float2(h0), f1 = __half22float2(h1);
            a0.x += f0.x; a0.y += f0.y;
            a1.x += f1.x; a1.y += f1.y;
        }
    }
    for (; e < cnt; e++) {
        int sN = g_srcs[off + e];
        __half2 h0 = base[(size_t)sN * 64 + 2 * lane];
        __half2 h1 = base[(size_t)sN * 64 + 2 * lane + 1];
        float2 f0 = __half22float2(h0), f1 = __half22float2(h1);
        a0.x += f0.x; a0.y += f0.y;
        a1.x += f1.x; a1.y += f1.y;
    }
    float s = 1.0f / (float)(cnt > 0 ? cnt : 1);
    __half2 o0 = __floats2half2_rn(a0.x * s, a0.y * s);
    __half2 o1 = __floats2half2_rn(a1.x * s, a1.y * s);
    __half2* dst = (__half2*)g_agg16 + (size_t)w * 64 + 2 * lane;
    dst[0] = o0;
    dst[1] = o1;
}

// ---------------------------------------------------------------------------
// fp16 split helpers.
// ---------------------------------------------------------------------------
__device__ __forceinline__ uint32_t packh2(float a, float b) {
    __half2 h = __floats2half2_rn(a, b);
    return *(uint32_t*)&h;
}
__device__ __forceinline__ void split2h(float a, float b, uint32_t& h, uint32_t& l) {
    __half2 hh = __floats2half2_rn(a, b);
    h = *(uint32_t*)&hh;
    l = packh2(a - __half2float(__low2half(hh)),
               b - __half2float(__high2half(hh)));
}

__device__ __forceinline__ void mma_f16(float* c, uint32_t a0, uint32_t a1,
                                        uint32_t a2, uint32_t a3,
                                        uint32_t b0, uint32_t b1) {
    asm volatile(
        "mma.sync.aligned.m16n8k16.row.col.f32.f16.f16.f32 "
        "{%0,%1,%2,%3}, {%4,%5,%6,%7}, {%8,%9}, {%0,%1,%2,%3};"
        : "+f"(c[0]), "+f"(c[1]), "+f"(c[2]), "+f"(c[3])
        : "r"(a0), "r"(a1), "r"(a2), "r"(a3), "r"(b0), "r"(b1));
}

// ---------------------------------------------------------------------------
// Fused combine GEMM:
//   out = act( [x | agg0 | agg1] @ [Wroot;Wrel0;Wrel1] + b )
// Segment 0 (fp32 source): 2-term split. Segments 1/2 (fp16 agg): 1-term.
// 256 threads = 8 warps; warp w owns rows [16w,16w+16) x OUTC cols.
// ---------------------------------------------------------------------------
template <int OUTC, bool LAYER1>
__global__ void __launch_bounds__(256)
combine_mma_kernel(const float* __restrict__ Ax,
                   const float* __restrict__ Wroot,
                   const float* __restrict__ Wrel,
                   const float* __restrict__ bias,
                   float* __restrict__ out_param) {
    constexpr int NT = OUTC / 8;
    __shared__ uint32_t As_hi[128][20];   // [row][k-word], 2 f16/word, pad 4
    __shared__ uint32_t As_lo[128][20];   // only valid when seg==0
    __shared__ uint32_t Bs[OUTC][20];     // [n][k-word], single fp16

    const float* A0  = LAYER1 ? Ax : g_h;
    float*       out = LAYER1 ? g_h : out_param;

    int tid  = threadIdx.x;
    int wid  = tid >> 5;
    int lane = tid & 31;
    int m0   = blockIdx.x * 128;
    int mrow = wid * 16;

    float acc[NT][4];
#pragma unroll
    for (int i = 0; i < NT; i++)
#pragma unroll
        for (int j = 0; j < 4; j++) acc[i][j] = 0.f;

    for (int c = 0; c < 12; c++) {
        int seg  = c >> 2;            // 0: root input (fp32), 1/2: fp16 means
        int krel = (c & 3) * 32;

        if (tid < 128) {
            int node = m0 + tid;
            bool valid = (node < NN);
            if (seg == 0) {
                const float4* src = (const float4*)(A0 + (size_t)node * 128 + krel);
#pragma unroll
                for (int i = 0; i < 8; i++) {
                    float4 v = valid ? src[i] : make_float4(0.f, 0.f, 0.f, 0.f);
                    uint32_t h0, l0, h1, l1;
                    split2h(v.x, v.y, h0, l0);
                    split2h(v.z, v.w, h1, l1);
                    As_hi[tid][2 * i + 0] = h0;
                    As_hi[tid][2 * i + 1] = h1;
                    As_lo[tid][2 * i + 0] = l0;
                    As_lo[tid][2 * i + 1] = l1;
                }
            } else {
                // fp16 rows: 32 halves = 16 words, raw copy.
                const uint4* src = (const uint4*)((const __half*)g_agg16 +
                    ((size_t)(seg - 1) * NN + node) * 128 + krel);
#pragma unroll
                for (int i = 0; i < 4; i++) {
                    uint4 v = valid ? src[i] : make_uint4(0u, 0u, 0u, 0u);
                    As_hi[tid][4 * i + 0] = v.x;
                    As_hi[tid][4 * i + 1] = v.y;
                    As_hi[tid][4 * i + 2] = v.z;
                    As_hi[tid][4 * i + 3] = v.w;
                }
            }
        } else if (tid - 128 < OUTC) {
            const float* Bsrc = (seg == 0) ? Wroot : (Wrel + (size_t)(seg - 1) * 128 * OUTC);
            int n = tid - 128;
#pragma unroll
            for (int g = 0; g < 16; g++) {
                float v0 = Bsrc[(size_t)(krel + 2 * g + 0) * OUTC + n];
                float v1 = Bsrc[(size_t)(krel + 2 * g + 1) * OUTC + n];
                Bs[n][g] = packh2(v0, v1);
            }
        }
        __syncthreads();

        bool two_term = (seg == 0);
#pragma unroll
        for (int k16 = 0; k16 < 2; k16++) {
            int wk = k16 * 8 + (lane & 3);
            int r0 = mrow + (lane >> 2);
            uint32_t ah0 = As_hi[r0][wk],     ah1 = As_hi[r0 + 8][wk];
            uint32_t ah2 = As_hi[r0][wk + 4], ah3 = As_hi[r0 + 8][wk + 4];
#pragma unroll
            for (int n8 = 0; n8 < NT; n8++) {
                int nr = n8 * 8 + (lane >> 2);
                uint32_t b0 = Bs[nr][wk], b1 = Bs[nr][wk + 4];
                mma_f16(acc[n8], ah0, ah1, ah2, ah3, b0, b1);
            }
            if (two_term) {
                uint32_t al0 = As_lo[r0][wk],     al1 = As_lo[r0 + 8][wk];
                uint32_t al2 = As_lo[r0][wk + 4], al3 = As_lo[r0 + 8][wk + 4];
#pragma unroll
                for (int n8 = 0; n8 < NT; n8++) {
                    int nr = n8 * 8 + (lane >> 2);
                    uint32_t b0 = Bs[nr][wk], b1 = Bs[nr][wk + 4];
                    mma_f16(acc[n8], al0, al1, al2, al3, b0, b1);
                }
            }
        }
        __syncthreads();
    }

    // Epilogue: c0={r, 2t}, c1={r, 2t+1}, c2/c3 at row+8.
    // Layer 1 additionally emits the fp16 copy of h for the layer-2 gather.
    int r0 = m0 + mrow + (lane >> 2);
#pragma unroll
    for (int n8 = 0; n8 < NT; n8++) {
        int col = n8 * 8 + 2 * (lane & 3);
        float b0 = bias[col], b1 = bias[col + 1];
        float2 o0, o1;
        o0.x = acc[n8][0] + b0; o0.y = acc[n8][1] + b1;
        o1.x = acc[n8][2] + b0; o1.y = acc[n8][3] + b1;
        if (LAYER1) {
            o0.x = fmaxf(o0.x, 0.f); o0.y = fmaxf(o0.y, 0.f);
            o1.x = fmaxf(o1.x, 0.f); o1.y = fmaxf(o1.y, 0.f);
        }
        if (r0 < NN) {
            *(float2*)(out + (size_t)r0 * OUTC + col) = o0;
            if (LAYER1)
                *((uint32_t*)g_h16 + (size_t)r0 * 64 + col / 2) = packh2(o0.x, o0.y);
        }
        if (r0 + 8 < NN) {
            *(float2*)(out + (size_t)(r0 + 8) * OUTC + col) = o1;
            if (LAYER1)
                *((uint32_t*)g_h16 + (size_t)(r0 + 8) * 64 + col / 2) = packh2(o1.x, o1.y);
        }
    }
}

// ---------------------------------------------------------------------------
// Row L2 normalize: one warp per node.
// ---------------------------------------------------------------------------
__global__ void normalize_kernel(float* __restrict__ out) {
    long long gtid = (long long)blockIdx.x * blockDim.x + threadIdx.x;
    int node = (int)(gtid >> 5);
    int lane = (int)(gtid & 31);
    if (node >= NN) return;
    float2* row = (float2*)(out + (size_t)node * COUT);
    float2 v = row[lane];
    float ss = v.x * v.x + v.y * v.y;
#pragma unroll
    for (int o = 16; o; o >>= 1) ss += __shfl_xor_sync(0xFFFFFFFFu, ss, o);
    float s = 1.0f / fmaxf(sqrtf(ss), 1e-12f);
    v.x *= s; v.y *= s;
    row[lane] = v;
}

// ---------------------------------------------------------------------------
extern "C" void kernel_launch(void* const* d_in, const int* in_sizes, int n_in,
                              void* d_out, int out_size) {
    const float* x       = (const float*)d_in[0];
    const void*  ei      = d_in[1];
    const void*  et      = d_in[2];
    const float* W1_rel  = (const float*)d_in[3];
    const float* W1_root = (const float*)d_in[4];
    const float* b1      = (const float*)d_in[5];
    const float* W2_rel  = (const float*)d_in[6];
    const float* W2_root = (const float*)d_in[7];
    const float* b2      = (const float*)d_in[8];
    float* out = (float*)d_out;

    const int MT = (NN + 127) / 128;   // 782

    detect_kernel<<<1, 1>>>(et);
    cvt_x_kernel<<<(int)(((size_t)NN * CIN / 2 + 255) / 256), 256>>>(x);

    // CSR build (once; reused by both layers)
    zero_icnt_kernel<<<(SCAN_N + 255) / 256, 256>>>();
    count_kernel<<<(NE + 255) / 256, 256>>>(ei, et);
    scan1_kernel<<<SNB, SBS>>>();
    scan2_kernel<<<1, SBS>>>();
    scan3_kernel<<<(SCAN_N + 255) / 256, 256>>>();
    place_kernel<<<(NE + 255) / 256, 256>>>(ei, et);

    // Layer 1
    gather_kernel<<<SCAN_N * 32 / 256, 256>>>(0);
    combine_mma_kernel<CHID, true><<<MT, 256>>>(x, W1_root, W1_rel, b1, nullptr);

    // Layer 2
    gather_kernel<<<SCAN_N * 32 / 256, 256>>>(1);
    combine_mma_kernel<COUT, false><<<MT, 256>>>(nullptr, W2_root, W2_rel, b2, out);

    normalize_kernel<<<(NN * 32 + 255) / 256, 256>>>(out);
}